// round 16
// baseline (speedup 1.0000x reference)
#include <cuda_runtime.h>
#include <cuda_fp16.h>
#include <cstdint>
#include <math.h>

#define NV 150000
#define NFACE 300000
#define L0 192
#define L1 96
#define L2DIM 48
#define KC 384            // padded conv K (375 -> 384)

typedef __half h16;

// ---------------- scratch (device globals; no allocation allowed) ----------
__device__ float g_nrm[NV * 3];
__device__ float g_vol1[L1 * L1 * L1];
__device__ float g_vol2[L2DIM * L2DIM * L2DIM];
__device__ h16   g_xcat[(size_t)NV * 256];      // fc1 out | lfc out
__device__ h16   g_h2[(size_t)NV * 512];
// pre-transposed fp16 weights, layout [N][K]
__device__ h16   g_wconv[128 * KC];
__device__ h16   g_wlfc[128 * 128];
__device__ h16   g_w2[512 * 256];
__device__ h16   g_w3[256 * 512];

// ---------------- small kernels --------------------------------------------
__global__ void k_zero(float* p, int n) {
    int i = blockIdx.x * blockDim.x + threadIdx.x;
    if (i < n) p[i] = 0.f;
}

__global__ void k_face_normals(const float* __restrict__ v, const int* __restrict__ f) {
    int i = blockIdx.x * blockDim.x + threadIdx.x;
    if (i >= NFACE) return;
    int i0 = f[i * 3 + 0], i1 = f[i * 3 + 1], i2 = f[i * 3 + 2];
    float p0x = v[i0 * 3], p0y = v[i0 * 3 + 1], p0z = v[i0 * 3 + 2];
    float p1x = v[i1 * 3], p1y = v[i1 * 3 + 1], p1z = v[i1 * 3 + 2];
    float p2x = v[i2 * 3], p2y = v[i2 * 3 + 1], p2z = v[i2 * 3 + 2];
    float ax = p1x - p0x, ay = p1y - p0y, az = p1z - p0z;
    float bx = p2x - p0x, by = p2y - p0y, bz = p2z - p0z;
    float cx = ay * bz - az * by;
    float cy = az * bx - ax * bz;
    float cz = ax * by - ay * bx;
    atomicAdd(&g_nrm[i0 * 3 + 0], cx); atomicAdd(&g_nrm[i0 * 3 + 1], cy); atomicAdd(&g_nrm[i0 * 3 + 2], cz);
    atomicAdd(&g_nrm[i1 * 3 + 0], cx); atomicAdd(&g_nrm[i1 * 3 + 1], cy); atomicAdd(&g_nrm[i1 * 3 + 2], cz);
    atomicAdd(&g_nrm[i2 * 3 + 0], cx); atomicAdd(&g_nrm[i2 * 3 + 1], cy); atomicAdd(&g_nrm[i2 * 3 + 2], cz);
}

__global__ void k_down(const float* __restrict__ src, float* __restrict__ dst, int s) {
    int i = blockIdx.x * blockDim.x + threadIdx.x;
    int tot = s * s * s;
    if (i >= tot) return;
    int c = i % s, b = (i / s) % s, a = i / (s * s);
    int S = 2 * s;
    float sum = 0.f;
#pragma unroll
    for (int da = 0; da < 2; da++)
#pragma unroll
        for (int db = 0; db < 2; db++)
#pragma unroll
            for (int dc = 0; dc < 2; dc++)
                sum += src[((size_t)(2 * a + da) * S + (2 * b + db)) * S + (2 * c + dc)];
    dst[i] = sum * 0.125f;
}

// merged weight prep (fp16, [N][K])
#define PREP_N0 (128 * KC)
#define PREP_N1 (PREP_N0 + 128 * 128)
#define PREP_N2 (PREP_N1 + 512 * 256)
#define PREP_N3 (PREP_N2 + 256 * 512)
__global__ void k_prep(const float* __restrict__ conv_w, const float* __restrict__ lfc_w,
                       const float* __restrict__ fc2_w, const float* __restrict__ fc3_w) {
    int i = blockIdx.x * blockDim.x + threadIdx.x;
    if (i < PREP_N0) {
        int o = i / KC, c = i % KC;
        g_wconv[i] = __float2half(c < 375 ? conv_w[o * 375 + c] : 0.f);
    } else if (i < PREP_N1) {
        int j = i - PREP_N0;
        int n = j / 128, k = j % 128;
        g_wlfc[j] = __float2half(lfc_w[(size_t)k * 128 + n]);
    } else if (i < PREP_N2) {
        int j = i - PREP_N1;
        int n = j / 256, k = j % 256;
        g_w2[j] = __float2half(fc2_w[(size_t)k * 512 + n]);
    } else if (i < PREP_N3) {
        int j = i - PREP_N2;
        int n = j / 512, k = j % 512;
        g_w3[j] = __float2half(fc3_w[(size_t)k * 256 + n]);
    }
}

// fc1 (6->128) + leaky
__global__ void k_fc1(const float* __restrict__ v, const float* __restrict__ w,
                      const float* __restrict__ b) {
    __shared__ float ws[6 * 128];
    __shared__ float bs[128];
    const int t = threadIdx.x;  // 128
    bs[t] = b[t];
#pragma unroll
    for (int i = 0; i < 6; i++) ws[i * 128 + t] = w[i * 128 + t];
    __syncthreads();
    for (int vid = blockIdx.x; vid < NV; vid += gridDim.x) {
        float in0 = v[vid * 3 + 0], in1 = v[vid * 3 + 1], in2 = v[vid * 3 + 2];
        float nx = g_nrm[vid * 3 + 0], ny = g_nrm[vid * 3 + 1], nz = g_nrm[vid * 3 + 2];
        float nn = fmaxf(sqrtf(nx * nx + ny * ny + nz * nz), 1e-12f);
        float acc = bs[t];
        acc += in0 * ws[t];
        acc += in1 * ws[128 + t];
        acc += in2 * ws[256 + t];
        acc += (nx / nn) * ws[384 + t];
        acc += (ny / nn) * ws[512 + t];
        acc += (nz / nn) * ws[640 + t];
        float r = acc > 0.f ? acc : 0.15f * acc;
        g_xcat[(size_t)vid * 256 + t] = __float2half(r);
    }
}

// ---------------- MMA building blocks --------------------------------------
__device__ __forceinline__ uint32_t smem_u32(const void* p) {
    uint32_t a;
    asm("{ .reg .u64 t; cvta.to.shared.u64 t, %1; cvt.u32.u64 %0, t; }" : "=r"(a) : "l"(p));
    return a;
}
__device__ __forceinline__ void mma_h(uint32_t c[2], const uint32_t a[4], const uint32_t b[2]) {
    asm volatile(
        "mma.sync.aligned.m16n8k16.row.col.f16.f16.f16.f16 "
        "{%0,%1}, {%2,%3,%4,%5}, {%6,%7}, {%0,%1};\n"
        : "+r"(c[0]), "+r"(c[1])
        : "r"(a[0]), "r"(a[1]), "r"(a[2]), "r"(a[3]), "r"(b[0]), "r"(b[1]));
}
__device__ __forceinline__ void ldsm_x4(uint32_t r[4], uint32_t addr) {
    asm volatile("ldmatrix.sync.aligned.m8n8.x4.shared.b16 {%0,%1,%2,%3}, [%4];"
                 : "=r"(r[0]), "=r"(r[1]), "=r"(r[2]), "=r"(r[3]) : "r"(addr));
}

// f16-acc wide tile: warp computes 64x64, rows wm*64.., cols wn*64..
__device__ __forceinline__ void mma_tile64(uint32_t abase, uint32_t bbase,
                                           uint32_t acc[4][8][2],
                                           int wm, int wn, int quad, int lrow) {
#pragma unroll
    for (int ks = 0; ks < 4; ks++) {
        const int kc0 = ks * 2 + (quad >> 1);
        uint32_t afr[4][4];
        uint32_t bfr[4][4];
#pragma unroll
        for (int im = 0; im < 4; im++) {
            int row = wm * 64 + im * 16 + (quad & 1) * 8 + lrow;
            uint32_t addr = abase + (uint32_t)row * 128u
                          + (uint32_t)((kc0 ^ (row & 7)) << 4);
            ldsm_x4(afr[im], addr);
        }
#pragma unroll
        for (int ib = 0; ib < 4; ib++) {
            int n = wn * 64 + ib * 16 + (quad & 1) * 8 + lrow;
            uint32_t addr = bbase + (uint32_t)n * 128u
                          + (uint32_t)((kc0 ^ (n & 7)) << 4);
            ldsm_x4(bfr[ib], addr);
        }
#pragma unroll
        for (int im = 0; im < 4; im++)
#pragma unroll
            for (int in = 0; in < 8; in++) {
                uint32_t bb[2] = { bfr[in >> 1][in & 1], bfr[in >> 1][2 + (in & 1)] };
                mma_h(acc[im][in], afr[im], bb);
            }
    }
}

// ---------------- wide-stage loader (A 16KB + B 32KB) for fc2/fc34 ---------
#define WST 49152u
#define WSMEM (2 * 49152 + 1536)
#define WSP_OFF (2 * 49152)

__device__ __forceinline__ void issue_wide(uint32_t sbase, int stage,
                                           const h16* A, const h16* B,
                                           int bm, int bn, int M, int Kd,
                                           int k0, int t) {
#pragma unroll
    for (int i = 0; i < 4; i++) {
        int e = t + i * 256;
        int m = e >> 3, kc = e & 7;
        int gm = bm + m;
        int sz = (gm < M) ? 16 : 0;
        if (gm >= M) gm = M - 1;
        uint32_t dst = sbase + (uint32_t)stage * WST + (uint32_t)m * 128u
                     + (uint32_t)((kc ^ (m & 7)) << 4);
        const void* src = A + (size_t)gm * Kd + k0 + kc * 8;
        asm volatile("cp.async.cg.shared.global [%0], [%1], 16, %2;"
                     :: "r"(dst), "l"(src), "r"(sz));
    }
#pragma unroll
    for (int i = 0; i < 8; i++) {
        int e = t + i * 256;
        int n = e >> 3, kc = e & 7;
        uint32_t dst = sbase + (uint32_t)stage * WST + 16384u + (uint32_t)n * 128u
                     + (uint32_t)((kc ^ (n & 7)) << 4);
        const void* src = B + (size_t)(bn + n) * Kd + k0 + kc * 8;
        asm volatile("cp.async.cg.shared.global [%0], [%1], 16;"
                     :: "r"(dst), "l"(src));
    }
    asm volatile("cp.async.commit_group;");
}

// ---------------- fc2: 128x256 block tile, 2 n-passes ----------------------
__global__ __launch_bounds__(256, 2)
void k_fc2w(const h16* __restrict__ xcat, const h16* __restrict__ w2,
            const float* __restrict__ b2, h16* __restrict__ h2, int M) {
    extern __shared__ char sm[];
    const int t = threadIdx.x;
    const int wid = t >> 5, lane = t & 31;
    const int wm = wid & 1, wn = wid >> 1;
    const int bm = blockIdx.y * 128;
    const uint32_t sbase = smem_u32(sm);
    const int quad = lane >> 3, lrow = lane & 7;
    const int r = lane >> 2, c = lane & 3;

    issue_wide(sbase, 0, xcat, w2, bm, 0, M, 256, 0, t);

    uint32_t acc[4][8][2];
    for (int s = 0; s < 8; s++) {
        const int kt = s & 3;
        if (kt == 0) {
#pragma unroll
            for (int i = 0; i < 4; i++)
#pragma unroll
                for (int j = 0; j < 8; j++) { acc[i][j][0] = 0u; acc[i][j][1] = 0u; }
        }
        if (s + 1 < 8) {
            issue_wide(sbase, (s + 1) & 1, xcat, w2, bm, ((s + 1) >> 2) * 256, M, 256,
                       ((s + 1) & 3) * 64, t);
            asm volatile("cp.async.wait_group 1;");
        } else {
            asm volatile("cp.async.wait_group 0;");
        }
        __syncthreads();
        mma_tile64(sbase + (uint32_t)(s & 1) * WST,
                   sbase + (uint32_t)(s & 1) * WST + 16384u,
                   acc, wm, wn, quad, lrow);
        __syncthreads();

        if (kt == 3) {
            const int pass = s >> 2;
#pragma unroll
            for (int im = 0; im < 4; im++) {
                int gm0 = bm + wm * 64 + im * 16 + r;
#pragma unroll
                for (int in = 0; in < 8; in++) {
                    int gn = pass * 256 + wn * 64 + in * 8 + c * 2;
                    float bb0 = b2[gn], bb1 = b2[gn + 1];
                    float2 lo = __half22float2(*reinterpret_cast<__half2*>(&acc[im][in][0]));
                    float2 hi = __half22float2(*reinterpret_cast<__half2*>(&acc[im][in][1]));
                    float v0 = lo.x + bb0, v1 = lo.y + bb1;
                    float v2 = hi.x + bb0, v3 = hi.y + bb1;
                    v0 = v0 > 0.f ? v0 : 0.15f * v0;
                    v1 = v1 > 0.f ? v1 : 0.15f * v1;
                    v2 = v2 > 0.f ? v2 : 0.15f * v2;
                    v3 = v3 > 0.f ? v3 : 0.15f * v3;
                    if (gm0 < M) {
                        __half2 p = __floats2half2_rn(v0, v1);
                        *reinterpret_cast<uint32_t*>(h2 + (size_t)gm0 * 512 + gn) =
                            *reinterpret_cast<uint32_t*>(&p);
                    }
                    if (gm0 + 8 < M) {
                        __half2 p = __floats2half2_rn(v2, v3);
                        *reinterpret_cast<uint32_t*>(h2 + (size_t)(gm0 + 8) * 512 + gn) =
                            *reinterpret_cast<uint32_t*>(&p);
                    }
                }
            }
        }
    }
}

// ---------------- fc3 (single 128x256 pass) + fc4 + final -------------------
__global__ __launch_bounds__(256, 2)
void k_fc34w(const h16* __restrict__ A, const h16* __restrict__ w3,
             const float* __restrict__ b3, int M,
             const float* __restrict__ w4, const float* __restrict__ b4,
             const float* __restrict__ v, float* __restrict__ out) {
    extern __shared__ char sm[];
    const int t = threadIdx.x;
    const int wid = t >> 5, lane = t & 31;
    const int wm = wid & 1, wn = wid >> 1;
    const int bm = blockIdx.y * 128;
    const uint32_t sbase = smem_u32(sm);
    const int quad = lane >> 3, lrow = lane & 7;
    const int r = lane >> 2, c = lane & 3;
    float* sp = reinterpret_cast<float*>(sm + WSP_OFF);  // [128][3]

    for (int i = t; i < 384; i += 256) sp[i] = 0.f;

    uint32_t acc[4][8][2];
#pragma unroll
    for (int i = 0; i < 4; i++)
#pragma unroll
        for (int j = 0; j < 8; j++) { acc[i][j][0] = 0u; acc[i][j][1] = 0u; }

    const int nk = 8;  // K = 512
    issue_wide(sbase, 0, A, w3, bm, 0, M, 512, 0, t);
    for (int kt = 0; kt < nk; kt++) {
        if (kt + 1 < nk) {
            issue_wide(sbase, (kt + 1) & 1, A, w3, bm, 0, M, 512, (kt + 1) * 64, t);
            asm volatile("cp.async.wait_group 1;");
        } else {
            asm volatile("cp.async.wait_group 0;");
        }
        __syncthreads();
        mma_tile64(sbase + (uint32_t)(kt & 1) * WST,
                   sbase + (uint32_t)(kt & 1) * WST + 16384u,
                   acc, wm, wn, quad, lrow);
        __syncthreads();
    }

#pragma unroll
    for (int im = 0; im < 4; im++) {
#pragma unroll
        for (int half = 0; half < 2; half++) {
            int rowl = wm * 64 + im * 16 + r + half * 8;
            float s0 = 0.f, s1 = 0.f, s2 = 0.f;
#pragma unroll
            for (int in = 0; in < 8; in++) {
                float2 pr = __half22float2(*reinterpret_cast<__half2*>(&acc[im][in][half]));
#pragma unroll
                for (int pp = 0; pp < 2; pp++) {
                    int n = wn * 64 + in * 8 + c * 2 + pp;
                    float val = (pp == 0 ? pr.x : pr.y) + b3[n];
                    val = val > 0.f ? val : 0.15f * val;
                    s0 += val * w4[n * 3 + 0];
                    s1 += val * w4[n * 3 + 1];
                    s2 += val * w4[n * 3 + 2];
                }
            }
            atomicAdd(&sp[rowl * 3 + 0], s0);
            atomicAdd(&sp[rowl * 3 + 1], s1);
            atomicAdd(&sp[rowl * 3 + 2], s2);
        }
    }
    __syncthreads();

    for (int i = t; i < 384; i += 256) {
        int gm = bm + i / 3;
        int comp = i % 3;
        if (gm < M)
            out[gm * 3 + comp] = v[gm * 3 + comp] + 0.1f * tanhf(sp[i] + b4[comp]);
    }
}

// ---------------- fused gather + conv + lfc, 256-row blocks, f16 acc --------
// stage: A (256x64 gathered, 32KB) @ s*49152, B (wconv 128x64, 16KB) @ +32768
// tables: abase64 @ 98304 (6KB), ocs @ 104448 (1.5KB)
#define CW_ST  49152u
#define CW_B   32768u
#define CW_IDX 98304u
#define CW_OC  (98304u + 6144u)
#define CW_SMEM (98304 + 6144 + 1536)

__global__ __launch_bounds__(256, 2)
void k_convlfc(const float* __restrict__ v, const float* __restrict__ vol0,
               const h16* __restrict__ Wconv, const float* __restrict__ conv_b,
               const h16* __restrict__ Wlfc, const float* __restrict__ lfc_b,
               h16* __restrict__ xcat, int M) {
    extern __shared__ char sm[];
    const int t = threadIdx.x;
    const int wid = t >> 5, lane = t & 31;
    const int wm = wid >> 1, wn = wid & 1;  // 4 m-positions x 2 n-positions
    const int bm = blockIdx.y * 256;
    const uint32_t sbase = smem_u32(sm);
    const int quad = lane >> 3, lrow = lane & 7;
    const int r = lane >> 2, c = lane & 3;

    uint64_t* abase64 = reinterpret_cast<uint64_t*>(sm + CW_IDX);
    uint32_t* ocs = reinterpret_cast<uint32_t*>(sm + CW_OC);

    // prologue: 256 per-vertex corner addresses + offset table
    {
        int vid = min(bm + t, M - 1);
        float vx = v[vid * 3 + 0], vy = v[vid * 3 + 1], vz = v[vid * 3 + 2];
#pragma unroll
        for (int n = 0; n < 3; n++) {
            int dim = (n == 0) ? L0 : ((n == 1) ? L1 : L2DIM);
            float scale = (n == 0) ? 96.f : ((n == 1) ? 48.f : 24.f);
            int hi = dim - 3;
            int i0 = min(max((int)rintf((vx + 1.f) * scale), 2), hi) - 2;
            int i1 = min(max((int)rintf((vy + 1.f) * scale), 2), hi) - 2;
            int i2 = min(max((int)rintf((vz + 1.f) * scale), 2), hi) - 2;
            const float* vol = (n == 0) ? vol0 : ((n == 1) ? (const float*)g_vol1
                                                           : (const float*)g_vol2);
            abase64[t * 3 + n] = (uint64_t)(vol + ((size_t)i0 * dim + i1) * dim + i2);
        }
    }
    for (int cc = t; cc < 384; cc += 256) {
        uint32_t entry;
        if (cc < 375) {
            int n = (cc >= 250) ? 2 : ((cc >= 125) ? 1 : 0);
            int rr = cc - n * 125;
            int di = rr / 25, dj = (rr / 5) % 5, dk = rr % 5;
            int dim = (n == 0) ? L0 : ((n == 1) ? L1 : L2DIM);
            entry = (uint32_t)((di * dim + dj) * dim + dk) | ((uint32_t)n << 28);
        } else {
            entry = 3u << 28;
        }
        ocs[cc] = entry;
    }
    // B tile 0 (wconv kt=0)
    {
#pragma unroll
        for (int i = 0; i < 4; i++) {
            int e = t + i * 256;
            int n = e >> 3, kc = e & 7;
            uint32_t dst = sbase + CW_B + (uint32_t)n * 128u + (uint32_t)((kc ^ (n & 7)) << 4);
            const void* src = Wconv + (size_t)n * KC + kc * 8;
            asm volatile("cp.async.cg.shared.global [%0], [%1], 16;" :: "r"(dst), "l"(src));
        }
        asm volatile("cp.async.commit_group;");
    }
    __syncthreads();

    uint32_t acc[4][8][2];
#pragma unroll
    for (int i = 0; i < 4; i++)
#pragma unroll
        for (int j = 0; j < 8; j++) { acc[i][j][0] = 0u; acc[i][j][1] = 0u; }

    for (int kt = 0; kt < 6; kt++) {
        const int buf = kt & 1;
        // gather-fill A(buf): 256 rows x 64 k -> 8 chunks/thread
#pragma unroll
        for (int i = 0; i < 8; i++) {
            int e = t + i * 256;
            int row = e >> 3, q = e & 7;
            int c0 = kt * 64 + q * 8;
            uint32_t pk[4];
#pragma unroll
            for (int jj = 0; jj < 4; jj++) {
                float f01[2];
#pragma unroll
                for (int h = 0; h < 2; h++) {
                    uint32_t o = ocs[c0 + jj * 2 + h];
                    uint32_t n = o >> 28;
                    float val = 0.f;
                    if (n < 3) {
                        const float* base = reinterpret_cast<const float*>(abase64[row * 3 + n]);
                        val = __ldg(base + (o & 0x0FFFFFFFu));
                    }
                    f01[h] = val;
                }
                __half2 p = __floats2half2_rn(f01[0], f01[1]);
                pk[jj] = *reinterpret_cast<uint32_t*>(&p);
            }
            *reinterpret_cast<uint4*>(sm + buf * CW_ST + (uint32_t)row * 128u
                + (uint32_t)((q ^ (row & 7)) << 4)) =
                make_uint4(pk[0], pk[1], pk[2], pk[3]);
        }
        // prefetch next B tile
        if (kt < 5) {
#pragma unroll
            for (int i = 0; i < 4; i++) {
                int e = t + i * 256;
                int n = e >> 3, kc = e & 7;
                uint32_t dst = sbase + (uint32_t)(buf ^ 1) * CW_ST + CW_B
                             + (uint32_t)n * 128u + (uint32_t)((kc ^ (n & 7)) << 4);
                const void* src = Wconv + (size_t)n * KC + (kt + 1) * 64 + kc * 8;
                asm volatile("cp.async.cg.shared.global [%0], [%1], 16;" :: "r"(dst), "l"(src));
            }
            asm volatile("cp.async.commit_group;");
            asm volatile("cp.async.wait_group 1;");
        } else {
            asm volatile("cp.async.wait_group 0;");
        }
        __syncthreads();
        mma_tile64(sbase + (uint32_t)buf * CW_ST, sbase + (uint32_t)buf * CW_ST + CW_B,
                   acc, wm, wn, quad, lrow);
        __syncthreads();
    }

    // load wlfc into 65536..98304 (2 k-tiles of 16KB)
#pragma unroll
    for (int kt = 0; kt < 2; kt++) {
#pragma unroll
        for (int i = 0; i < 4; i++) {
            int e = t + i * 256;
            int n = e >> 3, kc = e & 7;
            uint32_t dst = sbase + 65536u + (uint32_t)kt * 16384u + (uint32_t)n * 128u
                         + (uint32_t)((kc ^ (n & 7)) << 4);
            const void* src = Wlfc + (size_t)n * 128 + kt * 64 + kc * 8;
            asm volatile("cp.async.cg.shared.global [%0], [%1], 16;"
                         :: "r"(dst), "l"(src));
        }
    }
    asm volatile("cp.async.commit_group;");

    // store conv result (+bias, fp16) into 0..65536:
    // for col n: ktile = n>>6; row m (0..255): offset kt*32768 + m*128 + swizzle
#pragma unroll
    for (int im = 0; im < 4; im++) {
#pragma unroll
        for (int in = 0; in < 8; in++) {
            int n = wn * 64 + in * 8 + c * 2;      // 0..127
            float b0 = conv_b[n], b1 = conv_b[n + 1];
            int ktile = n >> 6;
            int bcol = (n & 63) * 2;
            int chunk = bcol >> 4, within = bcol & 15;
#pragma unroll
            for (int half = 0; half < 2; half++) {
                int m = wm * 64 + im * 16 + r + half * 8;   // 0..255
                float2 pr = __half22float2(*reinterpret_cast<__half2*>(&acc[im][in][half]));
                __half2 p = __floats2half2_rn(pr.x + b0, pr.y + b1);
                uint32_t addr = sbase + (uint32_t)ktile * 32768u + (uint32_t)m * 128u
                              + (uint32_t)((chunk ^ (m & 7)) << 4) + (uint32_t)within;
                asm volatile("st.shared.b32 [%0], %1;" :: "r"(addr),
                             "r"(*reinterpret_cast<uint32_t*>(&p)));
            }
        }
    }
    asm volatile("cp.async.wait_group 0;");
    __syncthreads();

    // lfc: 2 k-tiles, A = conv result (rows 0..255), B = wlfc
    uint32_t acc2[4][8][2];
#pragma unroll
    for (int i = 0; i < 4; i++)
#pragma unroll
        for (int j = 0; j < 8; j++) { acc2[i][j][0] = 0u; acc2[i][j][1] = 0u; }
#pragma unroll
    for (int kt = 0; kt < 2; kt++)
        mma_tile64(sbase + (uint32_t)kt * 32768u, sbase + 65536u + (uint32_t)kt * 16384u,
                   acc2, wm, wn, quad, lrow);

    // epilogue to xcat[:,128:256]
#pragma unroll
    for (int im = 0; im < 4; im++) {
        int gm0 = bm + wm * 64 + im * 16 + r;
#pragma unroll
        for (int in = 0; in < 8; in++) {
            int gn = wn * 64 + in * 8 + c * 2;
            float b0 = lfc_b[gn], b1 = lfc_b[gn + 1];
            float2 lo = __half22float2(*reinterpret_cast<__half2*>(&acc2[im][in][0]));
            float2 hi = __half22float2(*reinterpret_cast<__half2*>(&acc2[im][in][1]));
            if (gm0 < M) {
                __half2 p = __floats2half2_rn(lo.x + b0, lo.y + b1);
                *reinterpret_cast<uint32_t*>(xcat + (size_t)gm0 * 256 + 128 + gn) =
                    *reinterpret_cast<uint32_t*>(&p);
            }
            if (gm0 + 8 < M) {
                __half2 p = __floats2half2_rn(hi.x + b0, hi.y + b1);
                *reinterpret_cast<uint32_t*>(xcat + (size_t)(gm0 + 8) * 256 + 128 + gn) =
                    *reinterpret_cast<uint32_t*>(&p);
            }
        }
    }
}

// ---------------- launch ----------------------------------------------------
extern "C" void kernel_launch(void* const* d_in, const int* in_sizes, int n_in,
                              void* d_out, int out_size) {
    const float* v      = (const float*)d_in[0];
    const int*   f      = (const int*)d_in[1];
    const float* volume = (const float*)d_in[2];
    const float* fc1_w  = (const float*)d_in[3];
    const float* fc1_b  = (const float*)d_in[4];
    const float* fc2_w  = (const float*)d_in[5];
    const float* fc2_b  = (const float*)d_in[6];
    const float* fc3_w  = (const float*)d_in[7];
    const float* fc3_b  = (const float*)d_in[8];
    const float* fc4_w  = (const float*)d_in[9];
    const float* fc4_b  = (const float*)d_in[10];
    const float* conv_w = (const float*)d_in[11];
    const float* conv_b = (const float*)d_in[12];
    const float* lfc_w  = (const float*)d_in[13];
    const float* lfc_b  = (const float*)d_in[14];
    float* out = (float*)d_out;

    float *p_nrm, *p_vol1, *p_vol2;
    h16 *p_xcat, *p_h2, *p_wconv, *p_wlfc, *p_w2, *p_w3;
    cudaGetSymbolAddress((void**)&p_nrm, g_nrm);
    cudaGetSymbolAddress((void**)&p_vol1, g_vol1);
    cudaGetSymbolAddress((void**)&p_vol2, g_vol2);
    cudaGetSymbolAddress((void**)&p_xcat, g_xcat);
    cudaGetSymbolAddress((void**)&p_h2, g_h2);
    cudaGetSymbolAddress((void**)&p_wconv, g_wconv);
    cudaGetSymbolAddress((void**)&p_wlfc, g_wlfc);
    cudaGetSymbolAddress((void**)&p_w2, g_w2);
    cudaGetSymbolAddress((void**)&p_w3, g_w3);

    cudaFuncSetAttribute((const void*)k_convlfc, cudaFuncAttributeMaxDynamicSharedMemorySize, CW_SMEM);
    cudaFuncSetAttribute((const void*)k_fc2w, cudaFuncAttributeMaxDynamicSharedMemorySize, WSMEM);
    cudaFuncSetAttribute((const void*)k_fc34w, cudaFuncAttributeMaxDynamicSharedMemorySize, WSMEM);

    // 1. normals
    k_zero<<<(NV * 3 + 255) / 256, 256>>>(p_nrm, NV * 3);
    k_face_normals<<<(NFACE + 255) / 256, 256>>>(v, f);

    // 2. volume pyramid
    k_down<<<(L1 * L1 * L1 + 255) / 256, 256>>>(volume, p_vol1, L1);
    k_down<<<(L2DIM * L2DIM * L2DIM + 255) / 256, 256>>>(p_vol1, p_vol2, L2DIM);

    // 3. merged weight prep (fp16)
    k_prep<<<(PREP_N3 + 255) / 256, 256>>>(conv_w, lfc_w, fc2_w, fc3_w);

    // 4. fc1 -> xcat[:, 0:128]
    k_fc1<<<1184, 128>>>(v, fc1_w, fc1_b);

    const int MB = (NV + 127) / 128;
    const int MB2 = (NV + 255) / 256;

    // 5. fused gather + conv + lfc (256-row blocks) -> xcat[:, 128:256]
    k_convlfc<<<dim3(1, MB2), 256, CW_SMEM>>>(v, volume, p_wconv, conv_b,
                                              p_wlfc, lfc_b, p_xcat, NV);
    // 6. fc2 (wide tile) -> h2
    k_fc2w<<<dim3(1, MB), 256, WSMEM>>>(p_xcat, p_w2, fc2_b, p_h2, NV);
    // 7. fc3 (wide) + fc4 + final
    k_fc34w<<<dim3(1, MB), 256, WSMEM>>>(p_h2, p_w3, fc3_b, NV, fc4_w, fc4_b, v, out);
}

// round 17
// speedup vs baseline: 1.2651x; 1.2651x over previous
#include <cuda_runtime.h>
#include <cuda_fp16.h>
#include <cstdint>
#include <math.h>

#define NV 150000
#define NFACE 300000
#define L0 192
#define L1 96
#define L2DIM 48
#define KC 384            // padded conv K (375 -> 384)

typedef __half h16;

// ---------------- scratch (device globals; no allocation allowed) ----------
__device__ float g_nrm[NV * 3];
__device__ float g_vol1[L1 * L1 * L1];
__device__ float g_vol2[L2DIM * L2DIM * L2DIM];
__device__ h16   g_xcat[(size_t)NV * 256];      // fc1 out | lfc out
__device__ h16   g_h2[(size_t)NV * 512];
// pre-transposed fp16 weights, layout [N][K]
__device__ h16   g_wconv[128 * KC];
__device__ h16   g_wlfc[128 * 128];
__device__ h16   g_w2[512 * 256];
__device__ h16   g_w3[256 * 512];

// ---------------- small kernels --------------------------------------------
__global__ void k_zero(float* p, int n) {
    int i = blockIdx.x * blockDim.x + threadIdx.x;
    if (i < n) p[i] = 0.f;
}

__global__ void k_face_normals(const float* __restrict__ v, const int* __restrict__ f) {
    int i = blockIdx.x * blockDim.x + threadIdx.x;
    if (i >= NFACE) return;
    int i0 = f[i * 3 + 0], i1 = f[i * 3 + 1], i2 = f[i * 3 + 2];
    float p0x = v[i0 * 3], p0y = v[i0 * 3 + 1], p0z = v[i0 * 3 + 2];
    float p1x = v[i1 * 3], p1y = v[i1 * 3 + 1], p1z = v[i1 * 3 + 2];
    float p2x = v[i2 * 3], p2y = v[i2 * 3 + 1], p2z = v[i2 * 3 + 2];
    float ax = p1x - p0x, ay = p1y - p0y, az = p1z - p0z;
    float bx = p2x - p0x, by = p2y - p0y, bz = p2z - p0z;
    float cx = ay * bz - az * by;
    float cy = az * bx - ax * bz;
    float cz = ax * by - ay * bx;
    atomicAdd(&g_nrm[i0 * 3 + 0], cx); atomicAdd(&g_nrm[i0 * 3 + 1], cy); atomicAdd(&g_nrm[i0 * 3 + 2], cz);
    atomicAdd(&g_nrm[i1 * 3 + 0], cx); atomicAdd(&g_nrm[i1 * 3 + 1], cy); atomicAdd(&g_nrm[i1 * 3 + 2], cz);
    atomicAdd(&g_nrm[i2 * 3 + 0], cx); atomicAdd(&g_nrm[i2 * 3 + 1], cy); atomicAdd(&g_nrm[i2 * 3 + 2], cz);
}

__global__ void k_down(const float* __restrict__ src, float* __restrict__ dst, int s) {
    int i = blockIdx.x * blockDim.x + threadIdx.x;
    int tot = s * s * s;
    if (i >= tot) return;
    int c = i % s, b = (i / s) % s, a = i / (s * s);
    int S = 2 * s;
    float sum = 0.f;
#pragma unroll
    for (int da = 0; da < 2; da++)
#pragma unroll
        for (int db = 0; db < 2; db++)
#pragma unroll
            for (int dc = 0; dc < 2; dc++)
                sum += src[((size_t)(2 * a + da) * S + (2 * b + db)) * S + (2 * c + dc)];
    dst[i] = sum * 0.125f;
}

// merged weight prep (fp16, [N][K])
#define PREP_N0 (128 * KC)
#define PREP_N1 (PREP_N0 + 128 * 128)
#define PREP_N2 (PREP_N1 + 512 * 256)
#define PREP_N3 (PREP_N2 + 256 * 512)
__global__ void k_prep(const float* __restrict__ conv_w, const float* __restrict__ lfc_w,
                       const float* __restrict__ fc2_w, const float* __restrict__ fc3_w) {
    int i = blockIdx.x * blockDim.x + threadIdx.x;
    if (i < PREP_N0) {
        int o = i / KC, c = i % KC;
        g_wconv[i] = __float2half(c < 375 ? conv_w[o * 375 + c] : 0.f);
    } else if (i < PREP_N1) {
        int j = i - PREP_N0;
        int n = j / 128, k = j % 128;
        g_wlfc[j] = __float2half(lfc_w[(size_t)k * 128 + n]);
    } else if (i < PREP_N2) {
        int j = i - PREP_N1;
        int n = j / 256, k = j % 256;
        g_w2[j] = __float2half(fc2_w[(size_t)k * 512 + n]);
    } else if (i < PREP_N3) {
        int j = i - PREP_N2;
        int n = j / 512, k = j % 512;
        g_w3[j] = __float2half(fc3_w[(size_t)k * 256 + n]);
    }
}

// fc1 (6->128) + leaky
__global__ void k_fc1(const float* __restrict__ v, const float* __restrict__ w,
                      const float* __restrict__ b) {
    __shared__ float ws[6 * 128];
    __shared__ float bs[128];
    const int t = threadIdx.x;  // 128
    bs[t] = b[t];
#pragma unroll
    for (int i = 0; i < 6; i++) ws[i * 128 + t] = w[i * 128 + t];
    __syncthreads();
    for (int vid = blockIdx.x; vid < NV; vid += gridDim.x) {
        float in0 = v[vid * 3 + 0], in1 = v[vid * 3 + 1], in2 = v[vid * 3 + 2];
        float nx = g_nrm[vid * 3 + 0], ny = g_nrm[vid * 3 + 1], nz = g_nrm[vid * 3 + 2];
        float nn = fmaxf(sqrtf(nx * nx + ny * ny + nz * nz), 1e-12f);
        float acc = bs[t];
        acc += in0 * ws[t];
        acc += in1 * ws[128 + t];
        acc += in2 * ws[256 + t];
        acc += (nx / nn) * ws[384 + t];
        acc += (ny / nn) * ws[512 + t];
        acc += (nz / nn) * ws[640 + t];
        float r = acc > 0.f ? acc : 0.15f * acc;
        g_xcat[(size_t)vid * 256 + t] = __float2half(r);
    }
}

// ---------------- MMA building blocks --------------------------------------
__device__ __forceinline__ uint32_t smem_u32(const void* p) {
    uint32_t a;
    asm("{ .reg .u64 t; cvta.to.shared.u64 t, %1; cvt.u32.u64 %0, t; }" : "=r"(a) : "l"(p));
    return a;
}
__device__ __forceinline__ void mma_h(uint32_t c[2], const uint32_t a[4], const uint32_t b[2]) {
    asm volatile(
        "mma.sync.aligned.m16n8k16.row.col.f16.f16.f16.f16 "
        "{%0,%1}, {%2,%3,%4,%5}, {%6,%7}, {%0,%1};\n"
        : "+r"(c[0]), "+r"(c[1])
        : "r"(a[0]), "r"(a[1]), "r"(a[2]), "r"(a[3]), "r"(b[0]), "r"(b[1]));
}
__device__ __forceinline__ void ldsm_x4(uint32_t r[4], uint32_t addr) {
    asm volatile("ldmatrix.sync.aligned.m8n8.x4.shared.b16 {%0,%1,%2,%3}, [%4];"
                 : "=r"(r[0]), "=r"(r[1]), "=r"(r[2]), "=r"(r[3]) : "r"(addr));
}

// f16-acc tile (128x128 block, 8 warps 64x32) — convlfc
__device__ __forceinline__ void mma_tile_h32(uint32_t abase, uint32_t bbase,
                                             uint32_t acc[4][4][2],
                                             int wm, int wn, int quad, int lrow) {
#pragma unroll
    for (int ks = 0; ks < 4; ks++) {
        const int kc0 = ks * 2 + (quad >> 1);
        uint32_t afr[4][4];
        uint32_t bfr[2][4];
#pragma unroll
        for (int im = 0; im < 4; im++) {
            int row = wm * 64 + im * 16 + (quad & 1) * 8 + lrow;
            uint32_t addr = abase + (uint32_t)row * 128u
                          + (uint32_t)((kc0 ^ (row & 7)) << 4);
            ldsm_x4(afr[im], addr);
        }
#pragma unroll
        for (int ib = 0; ib < 2; ib++) {
            int n = wn * 32 + ib * 16 + (quad & 1) * 8 + lrow;
            uint32_t addr = bbase + (uint32_t)n * 128u
                          + (uint32_t)((kc0 ^ (n & 7)) << 4);
            ldsm_x4(bfr[ib], addr);
        }
#pragma unroll
        for (int im = 0; im < 4; im++)
#pragma unroll
            for (int in = 0; in < 4; in++) {
                uint32_t bb[2] = { bfr[in >> 1][in & 1], bfr[in >> 1][2 + (in & 1)] };
                mma_h(acc[im][in], afr[im], bb);
            }
    }
}

// f16-acc wide tile (128x256 block, 8 warps 64x64)
__device__ __forceinline__ void mma_tile64(uint32_t abase, uint32_t bbase,
                                           uint32_t acc[4][8][2],
                                           int wm, int wn, int quad, int lrow) {
#pragma unroll
    for (int ks = 0; ks < 4; ks++) {
        const int kc0 = ks * 2 + (quad >> 1);
        uint32_t afr[4][4];
        uint32_t bfr[4][4];
#pragma unroll
        for (int im = 0; im < 4; im++) {
            int row = wm * 64 + im * 16 + (quad & 1) * 8 + lrow;
            uint32_t addr = abase + (uint32_t)row * 128u
                          + (uint32_t)((kc0 ^ (row & 7)) << 4);
            ldsm_x4(afr[im], addr);
        }
#pragma unroll
        for (int ib = 0; ib < 4; ib++) {
            int n = wn * 64 + ib * 16 + (quad & 1) * 8 + lrow;
            uint32_t addr = bbase + (uint32_t)n * 128u
                          + (uint32_t)((kc0 ^ (n & 7)) << 4);
            ldsm_x4(bfr[ib], addr);
        }
#pragma unroll
        for (int im = 0; im < 4; im++)
#pragma unroll
            for (int in = 0; in < 8; in++) {
                uint32_t bb[2] = { bfr[in >> 1][in & 1], bfr[in >> 1][2 + (in & 1)] };
                mma_h(acc[im][in], afr[im], bb);
            }
    }
}

// ---------------- wide-stage loader (A 16KB + B 32KB) for fc2/fc34 ---------
#define WST 49152u
#define WSMEM (2 * 49152 + 1536)
#define WSP_OFF (2 * 49152)

__device__ __forceinline__ void issue_wide(uint32_t sbase, int stage,
                                           const h16* A, const h16* B,
                                           int bm, int bn, int M, int Kd,
                                           int k0, int t) {
#pragma unroll
    for (int i = 0; i < 4; i++) {
        int e = t + i * 256;
        int m = e >> 3, kc = e & 7;
        int gm = bm + m;
        int sz = (gm < M) ? 16 : 0;
        if (gm >= M) gm = M - 1;
        uint32_t dst = sbase + (uint32_t)stage * WST + (uint32_t)m * 128u
                     + (uint32_t)((kc ^ (m & 7)) << 4);
        const void* src = A + (size_t)gm * Kd + k0 + kc * 8;
        asm volatile("cp.async.cg.shared.global [%0], [%1], 16, %2;"
                     :: "r"(dst), "l"(src), "r"(sz));
    }
#pragma unroll
    for (int i = 0; i < 8; i++) {
        int e = t + i * 256;
        int n = e >> 3, kc = e & 7;
        uint32_t dst = sbase + (uint32_t)stage * WST + 16384u + (uint32_t)n * 128u
                     + (uint32_t)((kc ^ (n & 7)) << 4);
        const void* src = B + (size_t)(bn + n) * Kd + k0 + kc * 8;
        asm volatile("cp.async.cg.shared.global [%0], [%1], 16;"
                     :: "r"(dst), "l"(src));
    }
    asm volatile("cp.async.commit_group;");
}

// ---------------- fc2: 128x256 block tile, 2 n-passes ----------------------
__global__ __launch_bounds__(256, 2)
void k_fc2w(const h16* __restrict__ xcat, const h16* __restrict__ w2,
            const float* __restrict__ b2, h16* __restrict__ h2, int M) {
    extern __shared__ char sm[];
    const int t = threadIdx.x;
    const int wid = t >> 5, lane = t & 31;
    const int wm = wid & 1, wn = wid >> 1;
    const int bm = blockIdx.y * 128;
    const uint32_t sbase = smem_u32(sm);
    const int quad = lane >> 3, lrow = lane & 7;
    const int r = lane >> 2, c = lane & 3;

    issue_wide(sbase, 0, xcat, w2, bm, 0, M, 256, 0, t);

    uint32_t acc[4][8][2];
    for (int s = 0; s < 8; s++) {
        const int kt = s & 3;
        if (kt == 0) {
#pragma unroll
            for (int i = 0; i < 4; i++)
#pragma unroll
                for (int j = 0; j < 8; j++) { acc[i][j][0] = 0u; acc[i][j][1] = 0u; }
        }
        if (s + 1 < 8) {
            issue_wide(sbase, (s + 1) & 1, xcat, w2, bm, ((s + 1) >> 2) * 256, M, 256,
                       ((s + 1) & 3) * 64, t);
            asm volatile("cp.async.wait_group 1;");
        } else {
            asm volatile("cp.async.wait_group 0;");
        }
        __syncthreads();
        mma_tile64(sbase + (uint32_t)(s & 1) * WST,
                   sbase + (uint32_t)(s & 1) * WST + 16384u,
                   acc, wm, wn, quad, lrow);
        __syncthreads();

        if (kt == 3) {
            const int pass = s >> 2;
#pragma unroll
            for (int im = 0; im < 4; im++) {
                int gm0 = bm + wm * 64 + im * 16 + r;
#pragma unroll
                for (int in = 0; in < 8; in++) {
                    int gn = pass * 256 + wn * 64 + in * 8 + c * 2;
                    float bb0 = b2[gn], bb1 = b2[gn + 1];
                    float2 lo = __half22float2(*reinterpret_cast<__half2*>(&acc[im][in][0]));
                    float2 hi = __half22float2(*reinterpret_cast<__half2*>(&acc[im][in][1]));
                    float v0 = lo.x + bb0, v1 = lo.y + bb1;
                    float v2 = hi.x + bb0, v3 = hi.y + bb1;
                    v0 = v0 > 0.f ? v0 : 0.15f * v0;
                    v1 = v1 > 0.f ? v1 : 0.15f * v1;
                    v2 = v2 > 0.f ? v2 : 0.15f * v2;
                    v3 = v3 > 0.f ? v3 : 0.15f * v3;
                    if (gm0 < M) {
                        __half2 p = __floats2half2_rn(v0, v1);
                        *reinterpret_cast<uint32_t*>(h2 + (size_t)gm0 * 512 + gn) =
                            *reinterpret_cast<uint32_t*>(&p);
                    }
                    if (gm0 + 8 < M) {
                        __half2 p = __floats2half2_rn(v2, v3);
                        *reinterpret_cast<uint32_t*>(h2 + (size_t)(gm0 + 8) * 512 + gn) =
                            *reinterpret_cast<uint32_t*>(&p);
                    }
                }
            }
        }
    }
}

// ---------------- fc3 (single 128x256 pass) + fc4 + final -------------------
__global__ __launch_bounds__(256, 2)
void k_fc34w(const h16* __restrict__ A, const h16* __restrict__ w3,
             const float* __restrict__ b3, int M,
             const float* __restrict__ w4, const float* __restrict__ b4,
             const float* __restrict__ v, float* __restrict__ out) {
    extern __shared__ char sm[];
    const int t = threadIdx.x;
    const int wid = t >> 5, lane = t & 31;
    const int wm = wid & 1, wn = wid >> 1;
    const int bm = blockIdx.y * 128;
    const uint32_t sbase = smem_u32(sm);
    const int quad = lane >> 3, lrow = lane & 7;
    const int r = lane >> 2, c = lane & 3;
    float* sp = reinterpret_cast<float*>(sm + WSP_OFF);  // [128][3]

    for (int i = t; i < 384; i += 256) sp[i] = 0.f;

    uint32_t acc[4][8][2];
#pragma unroll
    for (int i = 0; i < 4; i++)
#pragma unroll
        for (int j = 0; j < 8; j++) { acc[i][j][0] = 0u; acc[i][j][1] = 0u; }

    const int nk = 8;  // K = 512
    issue_wide(sbase, 0, A, w3, bm, 0, M, 512, 0, t);
    for (int kt = 0; kt < nk; kt++) {
        if (kt + 1 < nk) {
            issue_wide(sbase, (kt + 1) & 1, A, w3, bm, 0, M, 512, (kt + 1) * 64, t);
            asm volatile("cp.async.wait_group 1;");
        } else {
            asm volatile("cp.async.wait_group 0;");
        }
        __syncthreads();
        mma_tile64(sbase + (uint32_t)(kt & 1) * WST,
                   sbase + (uint32_t)(kt & 1) * WST + 16384u,
                   acc, wm, wn, quad, lrow);
        __syncthreads();
    }

#pragma unroll
    for (int im = 0; im < 4; im++) {
#pragma unroll
        for (int half = 0; half < 2; half++) {
            int rowl = wm * 64 + im * 16 + r + half * 8;
            float s0 = 0.f, s1 = 0.f, s2 = 0.f;
#pragma unroll
            for (int in = 0; in < 8; in++) {
                float2 pr = __half22float2(*reinterpret_cast<__half2*>(&acc[im][in][half]));
#pragma unroll
                for (int pp = 0; pp < 2; pp++) {
                    int n = wn * 64 + in * 8 + c * 2 + pp;
                    float val = (pp == 0 ? pr.x : pr.y) + b3[n];
                    val = val > 0.f ? val : 0.15f * val;
                    s0 += val * w4[n * 3 + 0];
                    s1 += val * w4[n * 3 + 1];
                    s2 += val * w4[n * 3 + 2];
                }
            }
            atomicAdd(&sp[rowl * 3 + 0], s0);
            atomicAdd(&sp[rowl * 3 + 1], s1);
            atomicAdd(&sp[rowl * 3 + 2], s2);
        }
    }
    __syncthreads();

    for (int i = t; i < 384; i += 256) {
        int gm = bm + i / 3;
        int comp = i % 3;
        if (gm < M)
            out[gm * 3 + comp] = v[gm * 3 + comp] + 0.1f * tanhf(sp[i] + b4[comp]);
    }
}

// ---------------- fused gather + conv (K=384) + lfc (K=128), f16 acc --------
#define CG_TILE 16384u
#define CG_B0   32768u
#define CG_IDX  65536u
#define CG_OC   (65536u + 3072u)
#define CG_SMEM (65536 + 3072 + 1536)

__global__ __launch_bounds__(256, 2)
void k_convlfc(const float* __restrict__ v, const float* __restrict__ vol0,
               const h16* __restrict__ Wconv, const float* __restrict__ conv_b,
               const h16* __restrict__ Wlfc, const float* __restrict__ lfc_b,
               h16* __restrict__ xcat, int M) {
    extern __shared__ char sm[];
    const int t = threadIdx.x;
    const int wid = t >> 5, lane = t & 31;
    const int wm = wid & 1, wn = wid >> 1;
    const int bm = blockIdx.y * 128;
    const uint32_t sbase = smem_u32(sm);
    const int quad = lane >> 3, lrow = lane & 7;
    const int r = lane >> 2, c = lane & 3;

    uint64_t* abase64 = reinterpret_cast<uint64_t*>(sm + CG_IDX);
    uint32_t* ocs = reinterpret_cast<uint32_t*>(sm + CG_OC);

    if (t < 128) {
        int vid = min(bm + t, M - 1);
        float vx = v[vid * 3 + 0], vy = v[vid * 3 + 1], vz = v[vid * 3 + 2];
#pragma unroll
        for (int n = 0; n < 3; n++) {
            int dim = (n == 0) ? L0 : ((n == 1) ? L1 : L2DIM);
            float scale = (n == 0) ? 96.f : ((n == 1) ? 48.f : 24.f);
            int hi = dim - 3;
            int i0 = min(max((int)rintf((vx + 1.f) * scale), 2), hi) - 2;
            int i1 = min(max((int)rintf((vy + 1.f) * scale), 2), hi) - 2;
            int i2 = min(max((int)rintf((vz + 1.f) * scale), 2), hi) - 2;
            const float* vol = (n == 0) ? vol0 : ((n == 1) ? (const float*)g_vol1
                                                           : (const float*)g_vol2);
            abase64[t * 3 + n] = (uint64_t)(vol + ((size_t)i0 * dim + i1) * dim + i2);
        }
    }
    for (int cc = t; cc < 384; cc += 256) {
        uint32_t entry;
        if (cc < 375) {
            int n = (cc >= 250) ? 2 : ((cc >= 125) ? 1 : 0);
            int rr = cc - n * 125;
            int di = rr / 25, dj = (rr / 5) % 5, dk = rr % 5;
            int dim = (n == 0) ? L0 : ((n == 1) ? L1 : L2DIM);
            entry = (uint32_t)((di * dim + dj) * dim + dk) | ((uint32_t)n << 28);
        } else {
            entry = 3u << 28;
        }
        ocs[cc] = entry;
    }
    {
#pragma unroll
        for (int i = 0; i < 4; i++) {
            int e = t + i * 256;
            int n = e >> 3, kc = e & 7;
            uint32_t dst = sbase + CG_B0 + (uint32_t)n * 128u + (uint32_t)((kc ^ (n & 7)) << 4);
            const void* src = Wconv + (size_t)n * KC + kc * 8;
            asm volatile("cp.async.cg.shared.global [%0], [%1], 16;" :: "r"(dst), "l"(src));
        }
        asm volatile("cp.async.commit_group;");
    }
    __syncthreads();

    uint32_t acc[4][4][2];
#pragma unroll
    for (int i = 0; i < 4; i++)
#pragma unroll
        for (int j = 0; j < 4; j++) { acc[i][j][0] = 0u; acc[i][j][1] = 0u; }

    for (int kt = 0; kt < 6; kt++) {
        const int buf = kt & 1;
#pragma unroll
        for (int i = 0; i < 4; i++) {
            int e = t + i * 256;
            int row = e >> 3, q = e & 7;
            int c0 = kt * 64 + q * 8;
            uint32_t pk[4];
#pragma unroll
            for (int jj = 0; jj < 4; jj++) {
                float f01[2];
#pragma unroll
                for (int h = 0; h < 2; h++) {
                    uint32_t o = ocs[c0 + jj * 2 + h];
                    uint32_t n = o >> 28;
                    float val = 0.f;
                    if (n < 3) {
                        const float* base = reinterpret_cast<const float*>(abase64[row * 3 + n]);
                        val = __ldg(base + (o & 0x0FFFFFFFu));
                    }
                    f01[h] = val;
                }
                __half2 p = __floats2half2_rn(f01[0], f01[1]);
                pk[jj] = *reinterpret_cast<uint32_t*>(&p);
            }
            *reinterpret_cast<uint4*>(sm + buf * CG_TILE + (uint32_t)row * 128u
                + (uint32_t)((q ^ (row & 7)) << 4)) =
                make_uint4(pk[0], pk[1], pk[2], pk[3]);
        }
        if (kt < 5) {
#pragma unroll
            for (int i = 0; i < 4; i++) {
                int e = t + i * 256;
                int n = e >> 3, kc = e & 7;
                uint32_t dst = sbase + CG_B0 + (uint32_t)(buf ^ 1) * CG_TILE
                             + (uint32_t)n * 128u + (uint32_t)((kc ^ (n & 7)) << 4);
                const void* src = Wconv + (size_t)n * KC + (kt + 1) * 64 + kc * 8;
                asm volatile("cp.async.cg.shared.global [%0], [%1], 16;" :: "r"(dst), "l"(src));
            }
            asm volatile("cp.async.commit_group;");
            asm volatile("cp.async.wait_group 1;");
        } else {
            asm volatile("cp.async.wait_group 0;");
        }
        __syncthreads();
        mma_tile_h32(sbase + (uint32_t)buf * CG_TILE, sbase + CG_B0 + (uint32_t)buf * CG_TILE,
                     acc, wm, wn, quad, lrow);
        __syncthreads();
    }

    // store conv result (+bias, fp16) into A tiles 0/1, swizzled
#pragma unroll
    for (int im = 0; im < 4; im++) {
#pragma unroll
        for (int in = 0; in < 4; in++) {
            int n = wn * 32 + in * 8 + c * 2;
            float b0 = conv_b[n], b1 = conv_b[n + 1];
            int tile = n >> 6;
            int bcol = (n & 63) * 2;
            int chunk = bcol >> 4, within = bcol & 15;
#pragma unroll
            for (int half = 0; half < 2; half++) {
                int m = wm * 64 + im * 16 + r + half * 8;
                float2 pr = __half22float2(*reinterpret_cast<__half2*>(&acc[im][in][half]));
                __half2 p = __floats2half2_rn(pr.x + b0, pr.y + b1);
                uint32_t addr = sbase + (uint32_t)tile * CG_TILE + (uint32_t)m * 128u
                              + (uint32_t)((chunk ^ (m & 7)) << 4) + (uint32_t)within;
                asm volatile("st.shared.b32 [%0], %1;" :: "r"(addr),
                             "r"(*reinterpret_cast<uint32_t*>(&p)));
            }
        }
    }

    // load wlfc into B tiles 0/1
#pragma unroll
    for (int kt = 0; kt < 2; kt++) {
#pragma unroll
        for (int i = 0; i < 4; i++) {
            int e = t + i * 256;
            int n = e >> 3, kc = e & 7;
            uint32_t dst = sbase + CG_B0 + (uint32_t)kt * CG_TILE + (uint32_t)n * 128u
                         + (uint32_t)((kc ^ (n & 7)) << 4);
            const void* src = Wlfc + (size_t)n * 128 + kt * 64 + kc * 8;
            asm volatile("cp.async.cg.shared.global [%0], [%1], 16;"
                         :: "r"(dst), "l"(src));
        }
    }
    asm volatile("cp.async.commit_group;");
    asm volatile("cp.async.wait_group 0;");
    __syncthreads();

    // lfc: 2 k-tiles from smem, f16 acc
    uint32_t acc2[4][4][2];
#pragma unroll
    for (int i = 0; i < 4; i++)
#pragma unroll
        for (int j = 0; j < 4; j++) { acc2[i][j][0] = 0u; acc2[i][j][1] = 0u; }
#pragma unroll
    for (int kt = 0; kt < 2; kt++)
        mma_tile_h32(sbase + (uint32_t)kt * CG_TILE, sbase + CG_B0 + (uint32_t)kt * CG_TILE,
                     acc2, wm, wn, quad, lrow);

    // epilogue to xcat[:,128:256]
#pragma unroll
    for (int im = 0; im < 4; im++) {
        int gm0 = bm + wm * 64 + im * 16 + r;
#pragma unroll
        for (int in = 0; in < 4; in++) {
            int gn = wn * 32 + in * 8 + c * 2;
            float b0 = lfc_b[gn], b1 = lfc_b[gn + 1];
            float2 lo = __half22float2(*reinterpret_cast<__half2*>(&acc2[im][in][0]));
            float2 hi = __half22float2(*reinterpret_cast<__half2*>(&acc2[im][in][1]));
            if (gm0 < M) {
                __half2 p = __floats2half2_rn(lo.x + b0, lo.y + b1);
                *reinterpret_cast<uint32_t*>(xcat + (size_t)gm0 * 256 + 128 + gn) =
                    *reinterpret_cast<uint32_t*>(&p);
            }
            if (gm0 + 8 < M) {
                __half2 p = __floats2half2_rn(hi.x + b0, hi.y + b1);
                *reinterpret_cast<uint32_t*>(xcat + (size_t)(gm0 + 8) * 256 + 128 + gn) =
                    *reinterpret_cast<uint32_t*>(&p);
            }
        }
    }
}

// ---------------- launch ----------------------------------------------------
extern "C" void kernel_launch(void* const* d_in, const int* in_sizes, int n_in,
                              void* d_out, int out_size) {
    const float* v      = (const float*)d_in[0];
    const int*   f      = (const int*)d_in[1];
    const float* volume = (const float*)d_in[2];
    const float* fc1_w  = (const float*)d_in[3];
    const float* fc1_b  = (const float*)d_in[4];
    const float* fc2_w  = (const float*)d_in[5];
    const float* fc2_b  = (const float*)d_in[6];
    const float* fc3_w  = (const float*)d_in[7];
    const float* fc3_b  = (const float*)d_in[8];
    const float* fc4_w  = (const float*)d_in[9];
    const float* fc4_b  = (const float*)d_in[10];
    const float* conv_w = (const float*)d_in[11];
    const float* conv_b = (const float*)d_in[12];
    const float* lfc_w  = (const float*)d_in[13];
    const float* lfc_b  = (const float*)d_in[14];
    float* out = (float*)d_out;

    float *p_nrm, *p_vol1, *p_vol2;
    h16 *p_xcat, *p_h2, *p_wconv, *p_wlfc, *p_w2, *p_w3;
    cudaGetSymbolAddress((void**)&p_nrm, g_nrm);
    cudaGetSymbolAddress((void**)&p_vol1, g_vol1);
    cudaGetSymbolAddress((void**)&p_vol2, g_vol2);
    cudaGetSymbolAddress((void**)&p_xcat, g_xcat);
    cudaGetSymbolAddress((void**)&p_h2, g_h2);
    cudaGetSymbolAddress((void**)&p_wconv, g_wconv);
    cudaGetSymbolAddress((void**)&p_wlfc, g_wlfc);
    cudaGetSymbolAddress((void**)&p_w2, g_w2);
    cudaGetSymbolAddress((void**)&p_w3, g_w3);

    cudaFuncSetAttribute((const void*)k_convlfc, cudaFuncAttributeMaxDynamicSharedMemorySize, CG_SMEM);
    cudaFuncSetAttribute((const void*)k_fc2w, cudaFuncAttributeMaxDynamicSharedMemorySize, WSMEM);
    cudaFuncSetAttribute((const void*)k_fc34w, cudaFuncAttributeMaxDynamicSharedMemorySize, WSMEM);

    // 1. normals
    k_zero<<<(NV * 3 + 255) / 256, 256>>>(p_nrm, NV * 3);
    k_face_normals<<<(NFACE + 255) / 256, 256>>>(v, f);

    // 2. volume pyramid
    k_down<<<(L1 * L1 * L1 + 255) / 256, 256>>>(volume, p_vol1, L1);
    k_down<<<(L2DIM * L2DIM * L2DIM + 255) / 256, 256>>>(p_vol1, p_vol2, L2DIM);

    // 3. merged weight prep (fp16)
    k_prep<<<(PREP_N3 + 255) / 256, 256>>>(conv_w, lfc_w, fc2_w, fc3_w);

    // 4. fc1 -> xcat[:, 0:128]
    k_fc1<<<1184, 128>>>(v, fc1_w, fc1_b);

    const int MB = (NV + 127) / 128;

    // 5. fused gather + conv + lfc -> xcat[:, 128:256]
    k_convlfc<<<dim3(1, MB), 256, CG_SMEM>>>(v, volume, p_wconv, conv_b,
                                             p_wlfc, lfc_b, p_xcat, NV);
    // 6. fc2 (wide tile) -> h2
    k_fc2w<<<dim3(1, MB), 256, WSMEM>>>(p_xcat, p_w2, fc2_b, p_h2, NV);
    // 7. fc3 (wide) + fc4 + final
    k_fc34w<<<dim3(1, MB), 256, WSMEM>>>(p_h2, p_w3, fc3_b, NV, fc4_w, fc4_b, v, out);
}